// round 2
// baseline (speedup 1.0000x reference)
#include <cuda_runtime.h>
#include <math.h>

#define Bc 8
#define Nc 1024
#define Mc 1024
#define Dc 1024
#define Hc 128
#define MBITS 32
#define NEG_INF __int_as_float(0xff800000)

static constexpr float kScale = 0.17677669529663687f; // 1/sqrt(32)

// ---------------- scratch (no allocations allowed) ----------------
__device__ float    g_qt[Bc * Nc * MBITS];   // tropical Q codes
__device__ float    g_qr[Bc * Nc * MBITS];   // real Q codes
__device__ unsigned g_qb[Bc * Nc];           // boolean Q bits
__device__ float    g_kt[Bc * Mc * MBITS];
__device__ float    g_kr[Bc * Mc * MBITS];
__device__ unsigned g_kb[Bc * Mc];
__device__ float    g_vp[Bc * Mc * Hc];      // V @ Wv

// ================================================================
// Kernel 1: fused Q (or K) projection: X[8192,1024] x {Wb,Wt,Wr}[1024,32]
// -> trop codes, real codes, packed boolean bits.
// Tile: 64 rows x 96 cols, BK=32, 256 threads, 4x6 microtile.
// ================================================================
__global__ __launch_bounds__(256) void proj_qk_kernel(
    const float* __restrict__ X,
    const float* __restrict__ Wb, const float* __restrict__ Wt,
    const float* __restrict__ Wr,
    float* __restrict__ oT, float* __restrict__ oR, unsigned* __restrict__ oB)
{
    __shared__ float As[64][33];
    __shared__ float Bs[32][96];
    __shared__ float sbool[64][33];

    const int tid = threadIdx.x;
    const int ty = tid >> 4;        // 0..15 -> 4 rows each
    const int tx = tid & 15;        // 0..15 -> 6 cols each
    const int row0 = blockIdx.x * 64;

    float acc[4][6];
#pragma unroll
    for (int i = 0; i < 4; i++)
#pragma unroll
        for (int j = 0; j < 6; j++) acc[i][j] = 0.f;

    for (int k0 = 0; k0 < Dc; k0 += 32) {
        // A tile: 64x32 floats, float4 loads
#pragma unroll
        for (int l = 0; l < 2; l++) {
            int idx = tid + l * 256;
            int r = idx >> 3, c = (idx & 7) * 4;
            float4 v = *(const float4*)(X + (size_t)(row0 + r) * Dc + k0 + c);
            As[r][c] = v.x; As[r][c + 1] = v.y; As[r][c + 2] = v.z; As[r][c + 3] = v.w;
        }
        // B tile: 32 k x 96 cols (cols 0-31 bool, 32-63 trop, 64-95 real)
#pragma unroll
        for (int l = 0; l < 12; l++) {
            int idx = tid + l * 256;
            int kk = idx / 96, j = idx % 96;
            const float* W = (j < 32) ? Wb : ((j < 64) ? Wt : Wr);
            Bs[kk][j] = W[(size_t)(k0 + kk) * 32 + (j & 31)];
        }
        __syncthreads();
#pragma unroll
        for (int kk = 0; kk < 32; kk++) {
            float a[4], bv[6];
#pragma unroll
            for (int i = 0; i < 4; i++) a[i] = As[ty * 4 + i][kk];
#pragma unroll
            for (int j = 0; j < 6; j++) bv[j] = Bs[kk][tx * 6 + j];
#pragma unroll
            for (int i = 0; i < 4; i++)
#pragma unroll
                for (int j = 0; j < 6; j++) acc[i][j] = fmaf(a[i], bv[j], acc[i][j]);
        }
        __syncthreads();
    }

    // scatter: trop/real to global, bool to smem for bit packing
#pragma unroll
    for (int i = 0; i < 4; i++) {
        int r = ty * 4 + i;
        int row = row0 + r;
#pragma unroll
        for (int j = 0; j < 6; j++) {
            int col = tx * 6 + j;
            float v = acc[i][j];
            if (col < 32)      sbool[r][col] = v;
            else if (col < 64) oT[(size_t)row * MBITS + (col - 32)] = v;
            else               oR[(size_t)row * MBITS + (col - 64)] = v;
        }
    }
    __syncthreads();
    if (tid < 64) {
        unsigned bits = 0;
#pragma unroll
        for (int j = 0; j < 32; j++)
            bits |= (sbool[tid][j] > 0.f ? 1u : 0u) << j;
        oB[row0 + tid] = bits;
    }
}

// ================================================================
// Kernel 2 (shared): C[rows,128] = A[rows,1024] x B[1024,128]
// Used for V@Wv (grid (128,1), bStride=0) and attn@VP (grid (16,8)).
// ================================================================
__global__ __launch_bounds__(256) void gemm128_kernel(
    const float* __restrict__ A, const float* __restrict__ B0,
    float* __restrict__ C, size_t bStride)
{
    __shared__ float As[64][33];
    __shared__ float Bs[32][128];

    const int tid = threadIdx.x;
    const int ty = tid >> 4;
    const int tx = tid & 15;
    const float* Bm = B0 + (size_t)blockIdx.y * bStride;
    const size_t row0 = ((size_t)blockIdx.y * gridDim.x + blockIdx.x) * 64;

    float acc[4][8];
#pragma unroll
    for (int i = 0; i < 4; i++)
#pragma unroll
        for (int j = 0; j < 8; j++) acc[i][j] = 0.f;

    for (int k0 = 0; k0 < 1024; k0 += 32) {
#pragma unroll
        for (int l = 0; l < 2; l++) {
            int idx = tid + l * 256;
            int r = idx >> 3, c = (idx & 7) * 4;
            float4 v = *(const float4*)(A + (row0 + r) * 1024 + k0 + c);
            As[r][c] = v.x; As[r][c + 1] = v.y; As[r][c + 2] = v.z; As[r][c + 3] = v.w;
        }
#pragma unroll
        for (int l = 0; l < 4; l++) {
            int idx = tid + l * 256;
            int kk = idx >> 5, c = (idx & 31) * 4;
            *(float4*)&Bs[kk][c] = *(const float4*)(Bm + (size_t)(k0 + kk) * 128 + c);
        }
        __syncthreads();
#pragma unroll
        for (int kk = 0; kk < 32; kk++) {
            float a[4];
#pragma unroll
            for (int i = 0; i < 4; i++) a[i] = As[ty * 4 + i][kk];
            float4 b0 = *(float4*)&Bs[kk][tx * 8];
            float4 b1 = *(float4*)&Bs[kk][tx * 8 + 4];
            float bb[8] = {b0.x, b0.y, b0.z, b0.w, b1.x, b1.y, b1.z, b1.w};
#pragma unroll
            for (int i = 0; i < 4; i++)
#pragma unroll
                for (int j = 0; j < 8; j++) acc[i][j] = fmaf(a[i], bb[j], acc[i][j]);
        }
        __syncthreads();
    }
#pragma unroll
    for (int i = 0; i < 4; i++) {
        float4 o0 = make_float4(acc[i][0], acc[i][1], acc[i][2], acc[i][3]);
        float4 o1 = make_float4(acc[i][4], acc[i][5], acc[i][6], acc[i][7]);
        float* cp = C + (row0 + ty * 4 + i) * 128 + tx * 8;
        *(float4*)cp = o0;
        *(float4*)(cp + 4) = o1;
    }
}

// ================================================================
// Kernel 3: fused monoid scores -> raw masked scaled scores.
// 64x64 tile per block, 256 threads, 4x4 pairs/thread.
// ================================================================
__global__ __launch_bounds__(256) void scores_kernel(
    const float* __restrict__ fw, const int* __restrict__ mask,
    float* __restrict__ attn)
{
    __shared__ float qt[64][32];
    __shared__ float qr[64][32];
    __shared__ float kts[32][68];   // transposed, padded
    __shared__ float krs[32][68];
    __shared__ unsigned qb_s[64];
    __shared__ unsigned kb_s[64];

    const int tid = threadIdx.x;
    const int b  = blockIdx.z;
    const int n0 = blockIdx.y * 64;
    const int m0 = blockIdx.x * 64;
    const int qbase = b * Nc + n0;
    const int kbase = b * Mc + m0;

    // load Q codes (row-major, float4)
#pragma unroll
    for (int l = 0; l < 2; l++) {
        int idx = tid + l * 256;
        int r = idx >> 3, c = (idx & 7) * 4;
        *(float4*)&qt[r][c] = *(const float4*)(g_qt + (size_t)(qbase + r) * MBITS + c);
        *(float4*)&qr[r][c] = *(const float4*)(g_qr + (size_t)(qbase + r) * MBITS + c);
    }
    // load K codes transposed
#pragma unroll
    for (int l = 0; l < 8; l++) {
        int idx = tid + l * 256;
        int r = idx >> 5, d = idx & 31;
        kts[d][r] = g_kt[(size_t)(kbase + r) * MBITS + d];
        krs[d][r] = g_kr[(size_t)(kbase + r) * MBITS + d];
    }
    if (tid < 64)            qb_s[tid]       = g_qb[qbase + tid];
    else if (tid < 128)      kb_s[tid - 64]  = g_kb[kbase + tid - 64];
    __syncthreads();

    const int tn0 = (tid >> 4) * 4;
    const int tm0 = (tid & 15) * 4;

    float tAcc[4][4], rAcc[4][4];
#pragma unroll
    for (int i = 0; i < 4; i++)
#pragma unroll
        for (int j = 0; j < 4; j++) { tAcc[i][j] = NEG_INF; rAcc[i][j] = 0.f; }

#pragma unroll
    for (int d0 = 0; d0 < 32; d0 += 4) {
        float qtl[4][4], qrl[4][4];
#pragma unroll
        for (int i = 0; i < 4; i++) {
            float4 t = *(float4*)&qt[tn0 + i][d0];
            float4 r = *(float4*)&qr[tn0 + i][d0];
            qtl[i][0] = t.x; qtl[i][1] = t.y; qtl[i][2] = t.z; qtl[i][3] = t.w;
            qrl[i][0] = r.x; qrl[i][1] = r.y; qrl[i][2] = r.z; qrl[i][3] = r.w;
        }
#pragma unroll
        for (int dd = 0; dd < 4; dd++) {
            float4 ktv = *(float4*)&kts[d0 + dd][tm0];
            float4 krv = *(float4*)&krs[d0 + dd][tm0];
            float ktl[4] = {ktv.x, ktv.y, ktv.z, ktv.w};
            float krl[4] = {krv.x, krv.y, krv.z, krv.w};
#pragma unroll
            for (int i = 0; i < 4; i++) {
                float qtd = qtl[i][dd];
                float qrd = qrl[i][dd];
#pragma unroll
                for (int j = 0; j < 4; j++) {
                    tAcc[i][j] = fmaxf(tAcc[i][j], qtd + ktl[j]);
                    rAcc[i][j] = fmaf(qrd, krl[j], rAcc[i][j]);
                }
            }
        }
    }

    // fusion weights softmax (3 elements)
    float f0 = fw[0], f1 = fw[1], f2 = fw[2];
    float fm = fmaxf(f0, fmaxf(f1, f2));
    float e0 = __expf(f0 - fm), e1 = __expf(f1 - fm), e2 = __expf(f2 - fm);
    float inv = 1.f / (e0 + e1 + e2);
    float w0 = e0 * inv, w1 = e1 * inv, w2 = e2 * inv;

    unsigned qbv[4], kbv[4];
#pragma unroll
    for (int i = 0; i < 4; i++) qbv[i] = qb_s[tn0 + i];
#pragma unroll
    for (int j = 0; j < 4; j++) kbv[j] = kb_s[tm0 + j];

#pragma unroll
    for (int i = 0; i < 4; i++) {
        size_t off = ((size_t)b * Nc + n0 + tn0 + i) * Mc + m0 + tm0;
        int4 mk = *(const int4*)(mask + off);
        float s0 = (w0 * (float)(32 - __popc(qbv[i] ^ kbv[0])) + w1 * tAcc[i][0] + w2 * rAcc[i][0]) * kScale;
        float s1 = (w0 * (float)(32 - __popc(qbv[i] ^ kbv[1])) + w1 * tAcc[i][1] + w2 * rAcc[i][1]) * kScale;
        float s2 = (w0 * (float)(32 - __popc(qbv[i] ^ kbv[2])) + w1 * tAcc[i][2] + w2 * rAcc[i][2]) * kScale;
        float s3 = (w0 * (float)(32 - __popc(qbv[i] ^ kbv[3])) + w1 * tAcc[i][3] + w2 * rAcc[i][3]) * kScale;
        float4 o;
        o.x = (mk.x == 0) ? NEG_INF : s0;
        o.y = (mk.y == 0) ? NEG_INF : s1;
        o.z = (mk.z == 0) ? NEG_INF : s2;
        o.w = (mk.w == 0) ? NEG_INF : s3;
        *(float4*)(attn + off) = o;
    }
}

// ================================================================
// Kernel 4: row softmax over M=1024, in place. One block per row.
// ================================================================
__global__ __launch_bounds__(256) void softmax_kernel(float* __restrict__ attn)
{
    __shared__ float red[8];
    const size_t row = blockIdx.x;
    float* p = attn + row * (size_t)Mc;
    const int tid = threadIdx.x;
    const int lane = tid & 31, wid = tid >> 5;

    float4 v = *(float4*)(p + tid * 4);
    float m = fmaxf(fmaxf(v.x, v.y), fmaxf(v.z, v.w));
#pragma unroll
    for (int o = 16; o > 0; o >>= 1) m = fmaxf(m, __shfl_xor_sync(0xffffffffu, m, o));
    if (lane == 0) red[wid] = m;
    __syncthreads();
    float bm = fmaxf(fmaxf(fmaxf(red[0], red[1]), fmaxf(red[2], red[3])),
                     fmaxf(fmaxf(red[4], red[5]), fmaxf(red[6], red[7])));
    __syncthreads();

    float4 e;
    e.x = __expf(v.x - bm); e.y = __expf(v.y - bm);
    e.z = __expf(v.z - bm); e.w = __expf(v.w - bm);
    float s = e.x + e.y + e.z + e.w;
#pragma unroll
    for (int o = 16; o > 0; o >>= 1) s += __shfl_xor_sync(0xffffffffu, s, o);
    if (lane == 0) red[wid] = s;
    __syncthreads();
    float ts = red[0] + red[1] + red[2] + red[3] + red[4] + red[5] + red[6] + red[7];
    float invs = 1.f / ts;
    e.x *= invs; e.y *= invs; e.z *= invs; e.w *= invs;
    *(float4*)(p + tid * 4) = e;
}

// ================================================================
extern "C" void kernel_launch(void* const* d_in, const int* in_sizes, int n_in,
                              void* d_out, int out_size)
{
    const float* Q   = (const float*)d_in[0];
    const float* K   = (const float*)d_in[1];
    const float* V   = (const float*)d_in[2];
    const float* Wqb = (const float*)d_in[3];
    const float* Wkb = (const float*)d_in[4];
    const float* Wqt = (const float*)d_in[5];
    const float* Wkt = (const float*)d_in[6];
    const float* Wqr = (const float*)d_in[7];
    const float* Wkr = (const float*)d_in[8];
    const float* Wv  = (const float*)d_in[9];
    const float* fw  = (const float*)d_in[10];
    const int*   mask = (const int*)d_in[11];

    float* out  = (float*)d_out;                             // [B,N,128]
    float* attn = (float*)d_out + (size_t)Bc * Nc * Hc;      // [B,N,M]

    float *qt, *qr, *kt, *kr, *vp;
    unsigned *qb, *kb;
    cudaGetSymbolAddress((void**)&qt, g_qt);
    cudaGetSymbolAddress((void**)&qr, g_qr);
    cudaGetSymbolAddress((void**)&qb, g_qb);
    cudaGetSymbolAddress((void**)&kt, g_kt);
    cudaGetSymbolAddress((void**)&kr, g_kr);
    cudaGetSymbolAddress((void**)&kb, g_kb);
    cudaGetSymbolAddress((void**)&vp, g_vp);

    // projections
    proj_qk_kernel<<<128, 256>>>(Q, Wqb, Wqt, Wqr, qt, qr, qb);
    proj_qk_kernel<<<128, 256>>>(K, Wkb, Wkt, Wkr, kt, kr, kb);
    gemm128_kernel<<<dim3(128, 1), 256>>>(V, Wv, vp, (size_t)0);

    // fused monoid scores (masked, scaled)
    scores_kernel<<<dim3(16, 16, 8), 256>>>(fw, mask, attn);

    // softmax over M
    softmax_kernel<<<Bc * Nc, 256>>>(attn);

    // out = attn @ VP  (per batch)
    gemm128_kernel<<<dim3(16, 8), 256>>>(attn, vp, out, (size_t)Mc * Hc);
}

// round 4
// speedup vs baseline: 1.2902x; 1.2902x over previous
#include <cuda_runtime.h>
#include <cuda_bf16.h>
#include <math.h>
#include <stdint.h>

#define Bc 8
#define Nc 1024
#define Mc 1024
#define Dc 1024
#define Hc 128
#define MBITS 32
#define NEG_INF __int_as_float(0xff800000)

static constexpr float kScale = 0.17677669529663687f; // 1/sqrt(32)

// ---------------- scratch (no allocations allowed) ----------------
__device__ float    g_qt[Bc * Nc * MBITS];
__device__ float    g_qr[Bc * Nc * MBITS];
__device__ unsigned g_qb[Bc * Nc];
__device__ float    g_kt[Bc * Mc * MBITS];
__device__ float    g_kr[Bc * Mc * MBITS];
__device__ unsigned g_kb[Bc * Mc];
__device__ float    g_wqT[96 * 1024];       // [j][d]: 0-31 bool, 32-63 trop, 64-95 real
__device__ float    g_wkT[96 * 1024];
__device__ float    g_wvT[128 * 1024];      // [h][d]
__device__ float    g_vpT[Bc * 128 * 1024]; // [(b*128+h)][m]

// ================================================================
// HMMA helpers (mma.sync m16n8k16 bf16, baseline sm_103 legal)
// ================================================================
__device__ __forceinline__ uint32_t smem_u32(const void* p) {
    return (uint32_t)__cvta_generic_to_shared(p);
}
__device__ __forceinline__ void ldsm_x4(uint32_t* r, uint32_t addr) {
    asm volatile("ldmatrix.sync.aligned.m8n8.x4.shared.b16 {%0,%1,%2,%3}, [%4];"
        : "=r"(r[0]), "=r"(r[1]), "=r"(r[2]), "=r"(r[3]) : "r"(addr));
}
__device__ __forceinline__ void mma16816(float* c, const uint32_t* a, const uint32_t* b) {
    asm volatile("mma.sync.aligned.m16n8k16.row.col.f32.bf16.bf16.f32 "
        "{%0,%1,%2,%3}, {%4,%5,%6,%7}, {%8,%9}, {%0,%1,%2,%3};"
        : "+f"(c[0]), "+f"(c[1]), "+f"(c[2]), "+f"(c[3])
        : "r"(a[0]), "r"(a[1]), "r"(a[2]), "r"(a[3]), "r"(b[0]), "r"(b[1]));
}

__device__ __forceinline__ void split_store(float4 v, char* ph, char* pl) {
    __nv_bfloat16 h0 = __float2bfloat16(v.x), h1 = __float2bfloat16(v.y);
    __nv_bfloat16 h2 = __float2bfloat16(v.z), h3 = __float2bfloat16(v.w);
    __nv_bfloat16 l0 = __float2bfloat16(v.x - __bfloat162float(h0));
    __nv_bfloat16 l1 = __float2bfloat16(v.y - __bfloat162float(h1));
    __nv_bfloat16 l2 = __float2bfloat16(v.z - __bfloat162float(h2));
    __nv_bfloat16 l3 = __float2bfloat16(v.w - __bfloat162float(h3));
    uint2 H, L;
    H.x = ((uint32_t)__bfloat16_as_ushort(h1) << 16) | __bfloat16_as_ushort(h0);
    H.y = ((uint32_t)__bfloat16_as_ushort(h3) << 16) | __bfloat16_as_ushort(h2);
    L.x = ((uint32_t)__bfloat16_as_ushort(l1) << 16) | __bfloat16_as_ushort(l0);
    L.y = ((uint32_t)__bfloat16_as_ushort(l3) << 16) | __bfloat16_as_ushort(l2);
    *(uint2*)ph = H;
    *(uint2*)pl = L;
}

// ================================================================
// Split-bf16 HMMA GEMM: C[128, NCOLS] = A[128,1024] x BT[NCOLS,1024]^T
// EPI: 0 = plain fp32 store [row][NCOLS] (NCOLS=128)
//      1 = projection epilogue (bool bits + exact fixup / trop / real), NCOLS=96
//      2 = VP transpose store -> vpT[(b*128+h)][m], NCOLS=128
// 256 threads = 8 warps (4 m x 2 n). Block K-chunk = 32 fp32.
// ================================================================
template<int NCOLS, int EPI>
__global__ __launch_bounds__(256, 1) void mma_kernel(
    const float* __restrict__ A0, const float* __restrict__ BT0,
    float* __restrict__ p0, float* __restrict__ p1, unsigned* __restrict__ p2,
    const float* __restrict__ A1, const float* __restrict__ BT1,
    float* __restrict__ q0, float* __restrict__ q1, unsigned* __restrict__ q2,
    int tilesPerSide, int batchB)
{
    extern __shared__ char smem[];
    constexpr int W   = NCOLS / 2;      // per-warp n width (48 or 64)
    constexpr int P   = W / 16;         // n-tile pairs (3 or 4)
    constexpr int SKP = 40;             // smem K stride (bf16) = 80B, conflict-free ldmatrix
    constexpr int ABUF = 128 * SKP * 2; // bytes per (buf,part)
    constexpr int BBUF = NCOLS * SKP * 2;
    constexpr int BF4  = (NCOLS * 8) / 256;
    constexpr int ST   = NCOLS + 4;     // stage stride (floats), 16B-aligned rows

    char* sA = smem;                    // [buf][part: hi,lo]
    char* sB = smem + 4 * ABUF;
    float* stage = (float*)smem;

    const int tid = threadIdx.x;
    const int wid = tid >> 5, lid = tid & 31;
    const int warpM = wid & 3, warpN = wid >> 2;

    const float* A = A0; const float* BT = BT0;
    float* po0 = p0; float* po1 = p1; unsigned* po2 = p2;
    int row0 = blockIdx.x * 128;
    if (EPI == 1 && blockIdx.x >= tilesPerSide) {
        row0 = (blockIdx.x - tilesPerSide) * 128;
        A = A1; BT = BT1; po0 = q0; po1 = q1; po2 = q2;
    }
    if (batchB) BT += (size_t)(row0 >> 10) * NCOLS * 1024;

    float acc[2][P][2][4];
#pragma unroll
    for (int t = 0; t < 2; t++)
#pragma unroll
        for (int p = 0; p < P; p++)
#pragma unroll
            for (int s = 0; s < 2; s++)
#pragma unroll
                for (int e = 0; e < 4; e++) acc[t][p][s][e] = 0.f;

    // per-thread fragment address components
    const int aRowB = warpM * 32 + (lid & 15);
    const int aKoff = (lid >> 4) << 3;
    const int bRowB = warpN * W + (lid & 7) + ((lid & 16) >> 1);
    const int bKoff = (lid & 8);

    float4 av[4]; float4 bv[BF4];
    // ---- preload + store chunk 0 ----
    {
        const float* Ap = A + (size_t)row0 * 1024;
#pragma unroll
        for (int i = 0; i < 4; i++) {
            int idx = i * 256 + tid; int r = idx >> 3, c4 = idx & 7;
            av[i] = *(const float4*)(Ap + (size_t)r * 1024 + c4 * 4);
        }
#pragma unroll
        for (int i = 0; i < BF4; i++) {
            int idx = i * 256 + tid; int r = idx >> 3, c4 = idx & 7;
            bv[i] = *(const float4*)(BT + (size_t)r * 1024 + c4 * 4);
        }
        char* ah = sA; char* al = sA + ABUF;
#pragma unroll
        for (int i = 0; i < 4; i++) {
            int idx = i * 256 + tid; int r = idx >> 3, c4 = idx & 7;
            int off = (r * SKP + c4 * 4) * 2;
            split_store(av[i], ah + off, al + off);
        }
        char* bh = sB; char* bl = sB + BBUF;
#pragma unroll
        for (int i = 0; i < BF4; i++) {
            int idx = i * 256 + tid; int r = idx >> 3, c4 = idx & 7;
            int off = (r * SKP + c4 * 4) * 2;
            split_store(bv[i], bh + off, bl + off);
        }
    }
    __syncthreads();

    for (int kc = 0; kc < 32; kc++) {
        const int buf = kc & 1;
        const bool more = (kc < 31);
        // ---- issue global loads for next chunk (latency hidden by mma) ----
        if (more) {
            const float* Ap = A + (size_t)row0 * 1024 + (kc + 1) * 32;
#pragma unroll
            for (int i = 0; i < 4; i++) {
                int idx = i * 256 + tid; int r = idx >> 3, c4 = idx & 7;
                av[i] = *(const float4*)(Ap + (size_t)r * 1024 + c4 * 4);
            }
            const float* Bp = BT + (kc + 1) * 32;
#pragma unroll
            for (int i = 0; i < BF4; i++) {
                int idx = i * 256 + tid; int r = idx >> 3, c4 = idx & 7;
                bv[i] = *(const float4*)(Bp + (size_t)r * 1024 + c4 * 4);
            }
        }
        // ---- mma on current buffer ----
        const uint32_t aH = smem_u32(sA + buf * 2 * ABUF);
        const uint32_t bH = smem_u32(sB + buf * 2 * BBUF);
#pragma unroll
        for (int ks = 0; ks < 2; ks++) {
            uint32_t ah[2][4], al[2][4];
            uint32_t aAddr = aH + (uint32_t)(aRowB * SKP + ks * 16 + aKoff) * 2;
            ldsm_x4(ah[0], aAddr);
            ldsm_x4(ah[1], aAddr + 16 * SKP * 2);
            ldsm_x4(al[0], aAddr + ABUF);
            ldsm_x4(al[1], aAddr + ABUF + 16 * SKP * 2);
#pragma unroll
            for (int p = 0; p < P; p++) {
                uint32_t bh[4], bl[4];
                uint32_t bAddr = bH + (uint32_t)((bRowB + p * 16) * SKP + ks * 16 + bKoff) * 2;
                ldsm_x4(bh, bAddr);
                ldsm_x4(bl, bAddr + BBUF);
#pragma unroll
                for (int t = 0; t < 2; t++) {
                    mma16816(acc[t][p][0], ah[t], &bh[0]);
                    mma16816(acc[t][p][1], ah[t], &bh[2]);
                    mma16816(acc[t][p][0], ah[t], &bl[0]);
                    mma16816(acc[t][p][1], ah[t], &bl[2]);
                    mma16816(acc[t][p][0], al[t], &bh[0]);
                    mma16816(acc[t][p][1], al[t], &bh[2]);
                }
            }
        }
        // ---- store next chunk into other buffer ----
        if (more) {
            const int nb = buf ^ 1;
            char* ah2 = sA + nb * 2 * ABUF; char* al2 = ah2 + ABUF;
#pragma unroll
            for (int i = 0; i < 4; i++) {
                int idx = i * 256 + tid; int r = idx >> 3, c4 = idx & 7;
                int off = (r * SKP + c4 * 4) * 2;
                split_store(av[i], ah2 + off, al2 + off);
            }
            char* bh2 = sB + nb * 2 * BBUF; char* bl2 = bh2 + BBUF;
#pragma unroll
            for (int i = 0; i < BF4; i++) {
                int idx = i * 256 + tid; int r = idx >> 3, c4 = idx & 7;
                int off = (r * SKP + c4 * 4) * 2;
                split_store(bv[i], bh2 + off, bl2 + off);
            }
        }
        __syncthreads();
    }

    // ---- stage C to smem (overwrites operand buffers; all mma done) ----
#pragma unroll
    for (int t = 0; t < 2; t++)
#pragma unroll
        for (int p = 0; p < P; p++)
#pragma unroll
            for (int s = 0; s < 2; s++) {
                const float* c = acc[t][p][s];
                int m = warpM * 32 + t * 16 + (lid >> 2);
                int n = warpN * W + p * 16 + s * 8 + (lid & 3) * 2;
                stage[m * ST + n]           = c[0];
                stage[m * ST + n + 1]       = c[1];
                stage[(m + 8) * ST + n]     = c[2];
                stage[(m + 8) * ST + n + 1] = c[3];
            }
    __syncthreads();

    if (EPI == 0) {
#pragma unroll
        for (int i = 0; i < 16; i++) {
            int idx = i * 256 + tid; int m = idx >> 5, c4 = idx & 31;
            *(float4*)(po0 + (size_t)(row0 + m) * 128 + c4 * 4) =
                *(const float4*)(stage + m * ST + c4 * 4);
        }
    } else if (EPI == 1) {
        // trop (cols 32-63) and real (cols 64-95)
#pragma unroll
        for (int i = 0; i < 8; i++) {
            int idx = i * 256 + tid; int m = idx >> 4, c4 = idx & 15;
            float4 v = *(const float4*)(stage + m * ST + 32 + c4 * 4);
            if (c4 < 8) *(float4*)(po0 + (size_t)(row0 + m) * 32 + c4 * 4) = v;
            else        *(float4*)(po1 + (size_t)(row0 + m) * 32 + (c4 - 8) * 4) = v;
        }
        // boolean bits (cols 0-31) with exact fp32 fixup near zero
        if (tid < 128) {
            const int row = row0 + tid;
            unsigned bits = 0;
#pragma unroll 4
            for (int j = 0; j < 32; j++) {
                float v = stage[tid * ST + j];
                if (fabsf(v) < 2e-3f) {
                    const float* xr = A + (size_t)row * 1024;
                    const float* wr = BT + (size_t)j * 1024;
                    float s = 0.f;
#pragma unroll 8
                    for (int k = 0; k < 1024; k++) s = fmaf(xr[k], wr[k], s);
                    v = s;
                }
                bits |= (v > 0.f ? 1u : 0u) << j;
            }
            po2[row] = bits;
        }
    } else { // EPI == 2: transpose store vpT[(b*128+h)][m]
        const int b = row0 >> 10;
        const int m0 = row0 & 1023;
        const int h = tid & 127, half = tid >> 7;
        float* vpt = po0 + ((size_t)b * 128 + h) * 1024 + m0 + half * 64;
#pragma unroll 4
        for (int mm = 0; mm < 64; mm += 4) {
            int mb = half * 64 + mm;
            float4 v = make_float4(stage[(mb + 0) * ST + h], stage[(mb + 1) * ST + h],
                                   stage[(mb + 2) * ST + h], stage[(mb + 3) * ST + h]);
            *(float4*)(vpt + mm) = v;
        }
    }
}

// ================================================================
// W transpose prep: wqT[j][d], wkT[j][d] (96x1024), wvT[h][d] (128x1024)
// ================================================================
__global__ __launch_bounds__(256) void wprep_kernel(
    const float* __restrict__ Wqb, const float* __restrict__ Wqt, const float* __restrict__ Wqr,
    const float* __restrict__ Wkb, const float* __restrict__ Wkt, const float* __restrict__ Wkr,
    const float* __restrict__ Wv)
{
    int i = blockIdx.x * 256 + threadIdx.x;
    const int NQ = 96 * 1024;
    if (i < NQ) {
        int j = i >> 10, d = i & 1023;
        const float* W = (j < 32) ? Wqb : ((j < 64) ? Wqt : Wqr);
        g_wqT[i] = W[(size_t)d * 32 + (j & 31)];
    } else if (i < 2 * NQ) {
        int ii = i - NQ;
        int j = ii >> 10, d = ii & 1023;
        const float* W = (j < 32) ? Wkb : ((j < 64) ? Wkt : Wkr);
        g_wkT[ii] = W[(size_t)d * 32 + (j & 31)];
    } else if (i < 2 * NQ + 128 * 1024) {
        int ii = i - 2 * NQ;
        int j = ii >> 10, d = ii & 1023;
        g_wvT[ii] = Wv[(size_t)d * 128 + j];
    }
}

// ================================================================
// Fused monoid scores (unchanged from passing version)
// ================================================================
__global__ __launch_bounds__(256) void scores_kernel(
    const float* __restrict__ fw, const int* __restrict__ mask,
    float* __restrict__ attn)
{
    __shared__ float qt[64][32];
    __shared__ float qr[64][32];
    __shared__ float kts[32][68];
    __shared__ float krs[32][68];
    __shared__ unsigned qb_s[64];
    __shared__ unsigned kb_s[64];

    const int tid = threadIdx.x;
    const int b  = blockIdx.z;
    const int n0 = blockIdx.y * 64;
    const int m0 = blockIdx.x * 64;
    const int qbase = b * Nc + n0;
    const int kbase = b * Mc + m0;

#pragma unroll
    for (int l = 0; l < 2; l++) {
        int idx = tid + l * 256;
        int r = idx >> 3, c = (idx & 7) * 4;
        *(float4*)&qt[r][c] = *(const float4*)(g_qt + (size_t)(qbase + r) * MBITS + c);
        *(float4*)&qr[r][c] = *(const float4*)(g_qr + (size_t)(qbase + r) * MBITS + c);
    }
#pragma unroll
    for (int l = 0; l < 8; l++) {
        int idx = tid + l * 256;
        int r = idx >> 5, d = idx & 31;
        kts[d][r] = g_kt[(size_t)(kbase + r) * MBITS + d];
        krs[d][r] = g_kr[(size_t)(kbase + r) * MBITS + d];
    }
    if (tid < 64)            qb_s[tid]       = g_qb[qbase + tid];
    else if (tid < 128)      kb_s[tid - 64]  = g_kb[kbase + tid - 64];
    __syncthreads();

    const int tn0 = (tid >> 4) * 4;
    const int tm0 = (tid & 15) * 4;

    float tAcc[4][4], rAcc[4][4];
#pragma unroll
    for (int i = 0; i < 4; i++)
#pragma unroll
        for (int j = 0; j < 4; j++) { tAcc[i][j] = NEG_INF; rAcc[i][j] = 0.f; }

#pragma unroll
    for (int d0 = 0; d0 < 32; d0 += 4) {
        float qtl[4][4], qrl[4][4];
#pragma unroll
        for (int i = 0; i < 4; i++) {
            float4 t = *(float4*)&qt[tn0 + i][d0];
            float4 r = *(float4*)&qr[tn0 + i][d0];
            qtl[i][0] = t.x; qtl[i][1] = t.y; qtl[i][2] = t.z; qtl[i][3] = t.w;
            qrl[i][0] = r.x; qrl[i][1] = r.y; qrl[i][2] = r.z; qrl[i][3] = r.w;
        }
#pragma unroll
        for (int dd = 0; dd < 4; dd++) {
            float4 ktv = *(float4*)&kts[d0 + dd][tm0];
            float4 krv = *(float4*)&krs[d0 + dd][tm0];
            float ktl[4] = {ktv.x, ktv.y, ktv.z, ktv.w};
            float krl[4] = {krv.x, krv.y, krv.z, krv.w};
#pragma unroll
            for (int i = 0; i < 4; i++) {
                float qtd = qtl[i][dd];
                float qrd = qrl[i][dd];
#pragma unroll
                for (int j = 0; j < 4; j++) {
                    tAcc[i][j] = fmaxf(tAcc[i][j], qtd + ktl[j]);
                    rAcc[i][j] = fmaf(qrd, krl[j], rAcc[i][j]);
                }
            }
        }
    }

    float f0 = fw[0], f1 = fw[1], f2 = fw[2];
    float fm = fmaxf(f0, fmaxf(f1, f2));
    float e0 = __expf(f0 - fm), e1 = __expf(f1 - fm), e2 = __expf(f2 - fm);
    float inv = 1.f / (e0 + e1 + e2);
    float w0 = e0 * inv, w1 = e1 * inv, w2 = e2 * inv;

    unsigned qbv[4], kbv[4];
#pragma unroll
    for (int i = 0; i < 4; i++) qbv[i] = qb_s[tn0 + i];
#pragma unroll
    for (int j = 0; j < 4; j++) kbv[j] = kb_s[tm0 + j];

#pragma unroll
    for (int i = 0; i < 4; i++) {
        size_t off = ((size_t)b * Nc + n0 + tn0 + i) * Mc + m0 + tm0;
        int4 mk = *(const int4*)(mask + off);
        float s0 = (w0 * (float)(32 - __popc(qbv[i] ^ kbv[0])) + w1 * tAcc[i][0] + w2 * rAcc[i][0]) * kScale;
        float s1 = (w0 * (float)(32 - __popc(qbv[i] ^ kbv[1])) + w1 * tAcc[i][1] + w2 * rAcc[i][1]) * kScale;
        float s2 = (w0 * (float)(32 - __popc(qbv[i] ^ kbv[2])) + w1 * tAcc[i][2] + w2 * rAcc[i][2]) * kScale;
        float s3 = (w0 * (float)(32 - __popc(qbv[i] ^ kbv[3])) + w1 * tAcc[i][3] + w2 * rAcc[i][3]) * kScale;
        float4 o;
        o.x = (mk.x == 0) ? NEG_INF : s0;
        o.y = (mk.y == 0) ? NEG_INF : s1;
        o.z = (mk.z == 0) ? NEG_INF : s2;
        o.w = (mk.w == 0) ? NEG_INF : s3;
        *(float4*)(attn + off) = o;
    }
}

// ================================================================
// Row softmax over M=1024 in place (unchanged)
// ================================================================
__global__ __launch_bounds__(256) void softmax_kernel(float* __restrict__ attn)
{
    __shared__ float red[8];
    const size_t row = blockIdx.x;
    float* p = attn + row * (size_t)Mc;
    const int tid = threadIdx.x;
    const int lane = tid & 31, wid = tid >> 5;

    float4 v = *(float4*)(p + tid * 4);
    float m = fmaxf(fmaxf(v.x, v.y), fmaxf(v.z, v.w));
#pragma unroll
    for (int o = 16; o > 0; o >>= 1) m = fmaxf(m, __shfl_xor_sync(0xffffffffu, m, o));
    if (lane == 0) red[wid] = m;
    __syncthreads();
    float bm = fmaxf(fmaxf(fmaxf(red[0], red[1]), fmaxf(red[2], red[3])),
                     fmaxf(fmaxf(red[4], red[5]), fmaxf(red[6], red[7])));
    __syncthreads();

    float4 e;
    e.x = __expf(v.x - bm); e.y = __expf(v.y - bm);
    e.z = __expf(v.z - bm); e.w = __expf(v.w - bm);
    float s = e.x + e.y + e.z + e.w;
#pragma unroll
    for (int o = 16; o > 0; o >>= 1) s += __shfl_xor_sync(0xffffffffu, s, o);
    if (lane == 0) red[wid] = s;
    __syncthreads();
    float ts = red[0] + red[1] + red[2] + red[3] + red[4] + red[5] + red[6] + red[7];
    float invs = 1.f / ts;
    e.x *= invs; e.y *= invs; e.z *= invs; e.w *= invs;
    *(float4*)(p + tid * 4) = e;
}

// ================================================================
extern "C" void kernel_launch(void* const* d_in, const int* in_sizes, int n_in,
                              void* d_out, int out_size)
{
    const float* Q    = (const float*)d_in[0];
    const float* K    = (const float*)d_in[1];
    const float* V    = (const float*)d_in[2];
    const float* Wqb  = (const float*)d_in[3];
    const float* Wkb  = (const float*)d_in[4];
    const float* Wqt  = (const float*)d_in[5];
    const float* Wkt  = (const float*)d_in[6];
    const float* Wqr  = (const float*)d_in[7];
    const float* Wkr  = (const float*)d_in[8];
    const float* Wv   = (const float*)d_in[9];
    const float* fw   = (const float*)d_in[10];
    const int*   mask = (const int*)d_in[11];

    float* out  = (float*)d_out;                         // [B,N,128]
    float* attn = (float*)d_out + (size_t)Bc * Nc * Hc;  // [B,N,M]

    float *qt, *qr, *kt, *kr, *wqT, *wkT, *wvT, *vpT;
    unsigned *qb, *kb;
    cudaGetSymbolAddress((void**)&qt, g_qt);
    cudaGetSymbolAddress((void**)&qr, g_qr);
    cudaGetSymbolAddress((void**)&qb, g_qb);
    cudaGetSymbolAddress((void**)&kt, g_kt);
    cudaGetSymbolAddress((void**)&kr, g_kr);
    cudaGetSymbolAddress((void**)&kb, g_kb);
    cudaGetSymbolAddress((void**)&wqT, g_wqT);
    cudaGetSymbolAddress((void**)&wkT, g_wkT);
    cudaGetSymbolAddress((void**)&wvT, g_wvT);
    cudaGetSymbolAddress((void**)&vpT, g_vpT);

    // smem: A hi/lo x2bufs (40960) + B hi/lo x2bufs
    const int SMEM96  = 4 * 128 * 40 * 2 + 4 * 96 * 40 * 2;   // 71680
    const int SMEM128 = 4 * 128 * 40 * 2 + 4 * 128 * 40 * 2;  // 81920
    cudaFuncSetAttribute(mma_kernel<96, 1>,  cudaFuncAttributeMaxDynamicSharedMemorySize, SMEM96);
    cudaFuncSetAttribute(mma_kernel<128, 2>, cudaFuncAttributeMaxDynamicSharedMemorySize, SMEM128);
    cudaFuncSetAttribute(mma_kernel<128, 0>, cudaFuncAttributeMaxDynamicSharedMemorySize, SMEM128);

    // 1. weight transposes
    wprep_kernel<<<1280, 256>>>(Wqb, Wqt, Wqr, Wkb, Wkt, Wkr, Wv);

    // 2. Q + K projections (split-bf16 HMMA), 64 tiles each side
    mma_kernel<96, 1><<<128, 256, SMEM96>>>(
        Q, wqT, qt, qr, qb, K, wkT, kt, kr, kb, 64, 0);

    // 3. VP = V @ Wv, stored transposed as vpT[(b*128+h)][m]
    mma_kernel<128, 2><<<64, 256, SMEM128>>>(
        V, wvT, vpT, nullptr, nullptr, nullptr, nullptr, nullptr, nullptr, nullptr, 64, 0);

    // 4. fused monoid scores (masked, scaled)
    scores_kernel<<<dim3(16, 16, 8), 256>>>(fw, mask, attn);

    // 5. softmax over M
    softmax_kernel<<<Bc * Nc, 256>>>(attn);

    // 6. out = attn @ VP (batched B via vpT)
    mma_kernel<128, 0><<<64, 256, SMEM128>>>(
        attn, vpT, out, nullptr, nullptr, nullptr, nullptr, nullptr, nullptr, nullptr, 64, 1);
}

// round 5
// speedup vs baseline: 1.3465x; 1.0436x over previous
#include <cuda_runtime.h>
#include <cuda_bf16.h>
#include <math.h>
#include <stdint.h>

#define Bc 8
#define Nc 1024
#define Mc 1024
#define Dc 1024
#define Hc 128
#define MBITS 32
#define NEG_INF __int_as_float(0xff800000)

static constexpr float kScale = 0.17677669529663687f; // 1/sqrt(32)

// ---------------- scratch (no allocations allowed) ----------------
__device__ float    g_qt[Bc * Nc * MBITS];
__device__ float    g_qr[Bc * Nc * MBITS];
__device__ unsigned g_qb[Bc * Nc];
__device__ float    g_kt[Bc * Mc * MBITS];
__device__ float    g_kr[Bc * Mc * MBITS];
__device__ unsigned g_kb[Bc * Mc];
__device__ float    g_wqT[96 * 1024];       // [j][d]: 0-31 bool, 32-63 trop, 64-95 real
__device__ float    g_wkT[96 * 1024];
__device__ float    g_wvT[128 * 1024];      // [h][d]
__device__ float    g_vpT[Bc * 128 * 1024]; // [(b*128+h)][m]

// ================================================================
// HMMA helpers (mma.sync m16n8k16 bf16, baseline sm_103 legal)
// ================================================================
__device__ __forceinline__ uint32_t smem_u32(const void* p) {
    return (uint32_t)__cvta_generic_to_shared(p);
}
__device__ __forceinline__ void ldsm_x4(uint32_t* r, uint32_t addr) {
    asm volatile("ldmatrix.sync.aligned.m8n8.x4.shared.b16 {%0,%1,%2,%3}, [%4];"
        : "=r"(r[0]), "=r"(r[1]), "=r"(r[2]), "=r"(r[3]) : "r"(addr));
}
__device__ __forceinline__ void mma16816(float* c, const uint32_t* a, const uint32_t* b) {
    asm volatile("mma.sync.aligned.m16n8k16.row.col.f32.bf16.bf16.f32 "
        "{%0,%1,%2,%3}, {%4,%5,%6,%7}, {%8,%9}, {%0,%1,%2,%3};"
        : "+f"(c[0]), "+f"(c[1]), "+f"(c[2]), "+f"(c[3])
        : "r"(a[0]), "r"(a[1]), "r"(a[2]), "r"(a[3]), "r"(b[0]), "r"(b[1]));
}

__device__ __forceinline__ void split_store(float4 v, char* ph, char* pl) {
    __nv_bfloat16 h0 = __float2bfloat16(v.x), h1 = __float2bfloat16(v.y);
    __nv_bfloat16 h2 = __float2bfloat16(v.z), h3 = __float2bfloat16(v.w);
    __nv_bfloat16 l0 = __float2bfloat16(v.x - __bfloat162float(h0));
    __nv_bfloat16 l1 = __float2bfloat16(v.y - __bfloat162float(h1));
    __nv_bfloat16 l2 = __float2bfloat16(v.z - __bfloat162float(h2));
    __nv_bfloat16 l3 = __float2bfloat16(v.w - __bfloat162float(h3));
    uint2 H, L;
    H.x = ((uint32_t)__bfloat16_as_ushort(h1) << 16) | __bfloat16_as_ushort(h0);
    H.y = ((uint32_t)__bfloat16_as_ushort(h3) << 16) | __bfloat16_as_ushort(h2);
    L.x = ((uint32_t)__bfloat16_as_ushort(l1) << 16) | __bfloat16_as_ushort(l0);
    L.y = ((uint32_t)__bfloat16_as_ushort(l3) << 16) | __bfloat16_as_ushort(l2);
    *(uint2*)ph = H;
    *(uint2*)pl = L;
}

// ================================================================
// Split-bf16 HMMA GEMM: C[ROWS, NCOLS] = A[ROWS,1024] x BT[NCOLS,1024]^T
// ROWS = 64*TM.  8 warps: warpM in 0..3 (16*TM rows), warpN in 0..1 (NCOLS/2).
// EPI: 0 = plain fp32 store [row][NCOLS]
//      1 = projection epilogue (bool bits + exact fixup / trop / real), NCOLS=96
//      2 = VP transpose store -> vpT[(b*128+h)][m]
// ================================================================
template<int NCOLS, int EPI, int TM>
__global__ __launch_bounds__(256, 1) void mma_kernel(
    const float* __restrict__ A0, const float* __restrict__ BT0,
    float* __restrict__ p0, float* __restrict__ p1, unsigned* __restrict__ p2,
    const float* __restrict__ A1, const float* __restrict__ BT1,
    float* __restrict__ q0, float* __restrict__ q1, unsigned* __restrict__ q2,
    int tilesPerSide, int batchB)
{
    extern __shared__ char smem[];
    constexpr int ROWS = 64 * TM;
    constexpr int W   = NCOLS / 2;       // per-warpN n width (48 or 64)
    constexpr int P   = W / 16;          // n-tile pairs (3 or 4)
    constexpr int SKP = 40;              // smem K stride (bf16) = 80B, conflict-free ldmatrix
    constexpr int ABUF = ROWS * SKP * 2; // bytes per (buf,part)
    constexpr int BBUF = NCOLS * SKP * 2;
    constexpr int AF4  = 2 * TM;         // per-thread float4 loads for A
    constexpr int BF4  = NCOLS / 32;     // per-thread float4 loads for B
    constexpr int ST   = NCOLS + 4;      // stage stride (floats)

    char* sA = smem;                     // [buf][part: hi,lo]
    char* sB = smem + 4 * ABUF;
    float* stage = (float*)smem;

    const int tid = threadIdx.x;
    const int wid = tid >> 5, lid = tid & 31;
    const int warpM = wid & 3, warpN = wid >> 2;

    const float* A = A0; const float* BT = BT0;
    float* po0 = p0; float* po1 = p1; unsigned* po2 = p2;
    int row0 = blockIdx.x * ROWS;
    if (EPI == 1 && blockIdx.x >= tilesPerSide) {
        row0 = (blockIdx.x - tilesPerSide) * ROWS;
        A = A1; BT = BT1; po0 = q0; po1 = q1; po2 = q2;
    }
    if (batchB) BT += (size_t)(row0 >> 10) * NCOLS * 1024;

    float acc[TM][P][2][4];
#pragma unroll
    for (int t = 0; t < TM; t++)
#pragma unroll
        for (int p = 0; p < P; p++)
#pragma unroll
            for (int s = 0; s < 2; s++)
#pragma unroll
                for (int e = 0; e < 4; e++) acc[t][p][s][e] = 0.f;

    // per-thread fragment address components
    const int aRowB = warpM * (16 * TM) + (lid & 15);
    const int aKoff = (lid >> 4) << 3;
    const int bRowB = warpN * W + (lid & 7) + ((lid & 16) >> 1);
    const int bKoff = (lid & 8);

    float4 av[AF4]; float4 bv[BF4];
    // ---- preload + store chunk 0 ----
    {
        const float* Ap = A + (size_t)row0 * 1024;
#pragma unroll
        for (int i = 0; i < AF4; i++) {
            int idx = i * 256 + tid; int r = idx >> 3, c4 = idx & 7;
            av[i] = *(const float4*)(Ap + (size_t)r * 1024 + c4 * 4);
        }
#pragma unroll
        for (int i = 0; i < BF4; i++) {
            int idx = i * 256 + tid; int r = idx >> 3, c4 = idx & 7;
            bv[i] = *(const float4*)(BT + (size_t)r * 1024 + c4 * 4);
        }
        char* ah = sA; char* al = sA + ABUF;
#pragma unroll
        for (int i = 0; i < AF4; i++) {
            int idx = i * 256 + tid; int r = idx >> 3, c4 = idx & 7;
            int off = (r * SKP + c4 * 4) * 2;
            split_store(av[i], ah + off, al + off);
        }
        char* bh = sB; char* bl = sB + BBUF;
#pragma unroll
        for (int i = 0; i < BF4; i++) {
            int idx = i * 256 + tid; int r = idx >> 3, c4 = idx & 7;
            int off = (r * SKP + c4 * 4) * 2;
            split_store(bv[i], bh + off, bl + off);
        }
    }
    __syncthreads();

    for (int kc = 0; kc < 32; kc++) {
        const int buf = kc & 1;
        const bool more = (kc < 31);
        // ---- issue global loads for next chunk (latency hidden by mma) ----
        if (more) {
            const float* Ap = A + (size_t)row0 * 1024 + (kc + 1) * 32;
#pragma unroll
            for (int i = 0; i < AF4; i++) {
                int idx = i * 256 + tid; int r = idx >> 3, c4 = idx & 7;
                av[i] = *(const float4*)(Ap + (size_t)r * 1024 + c4 * 4);
            }
            const float* Bp = BT + (kc + 1) * 32;
#pragma unroll
            for (int i = 0; i < BF4; i++) {
                int idx = i * 256 + tid; int r = idx >> 3, c4 = idx & 7;
                bv[i] = *(const float4*)(Bp + (size_t)r * 1024 + c4 * 4);
            }
        }
        // ---- mma on current buffer ----
        const uint32_t aH = smem_u32(sA + buf * 2 * ABUF);
        const uint32_t bH = smem_u32(sB + buf * 2 * BBUF);
#pragma unroll
        for (int ks = 0; ks < 2; ks++) {
            uint32_t ah[TM][4], al[TM][4];
            uint32_t aAddr = aH + (uint32_t)(aRowB * SKP + ks * 16 + aKoff) * 2;
#pragma unroll
            for (int t = 0; t < TM; t++) {
                ldsm_x4(ah[t], aAddr + t * (16 * SKP * 2));
                ldsm_x4(al[t], aAddr + ABUF + t * (16 * SKP * 2));
            }
#pragma unroll
            for (int p = 0; p < P; p++) {
                uint32_t bh[4], bl[4];
                uint32_t bAddr = bH + (uint32_t)((bRowB + p * 16) * SKP + ks * 16 + bKoff) * 2;
                ldsm_x4(bh, bAddr);
                ldsm_x4(bl, bAddr + BBUF);
#pragma unroll
                for (int t = 0; t < TM; t++) {
                    mma16816(acc[t][p][0], ah[t], &bh[0]);
                    mma16816(acc[t][p][1], ah[t], &bh[2]);
                    mma16816(acc[t][p][0], ah[t], &bl[0]);
                    mma16816(acc[t][p][1], ah[t], &bl[2]);
                    mma16816(acc[t][p][0], al[t], &bh[0]);
                    mma16816(acc[t][p][1], al[t], &bh[2]);
                }
            }
        }
        // ---- store next chunk into other buffer ----
        if (more) {
            const int nb = buf ^ 1;
            char* ah2 = sA + nb * 2 * ABUF; char* al2 = ah2 + ABUF;
#pragma unroll
            for (int i = 0; i < AF4; i++) {
                int idx = i * 256 + tid; int r = idx >> 3, c4 = idx & 7;
                int off = (r * SKP + c4 * 4) * 2;
                split_store(av[i], ah2 + off, al2 + off);
            }
            char* bh2 = sB + nb * 2 * BBUF; char* bl2 = bh2 + BBUF;
#pragma unroll
            for (int i = 0; i < BF4; i++) {
                int idx = i * 256 + tid; int r = idx >> 3, c4 = idx & 7;
                int off = (r * SKP + c4 * 4) * 2;
                split_store(bv[i], bh2 + off, bl2 + off);
            }
        }
        __syncthreads();
    }

    // ---- stage C to smem (overwrites operand buffers; all mma done) ----
#pragma unroll
    for (int t = 0; t < TM; t++)
#pragma unroll
        for (int p = 0; p < P; p++)
#pragma unroll
            for (int s = 0; s < 2; s++) {
                const float* c = acc[t][p][s];
                int m = warpM * (16 * TM) + t * 16 + (lid >> 2);
                int n = warpN * W + p * 16 + s * 8 + (lid & 3) * 2;
                stage[m * ST + n]           = c[0];
                stage[m * ST + n + 1]       = c[1];
                stage[(m + 8) * ST + n]     = c[2];
                stage[(m + 8) * ST + n + 1] = c[3];
            }
    __syncthreads();

    if (EPI == 0) {
#pragma unroll
        for (int i = 0; i < (ROWS * NCOLS) / 1024; i++) {
            int idx = i * 256 + tid; int m = idx >> 5, c4 = idx & 31;
            *(float4*)(po0 + (size_t)(row0 + m) * 128 + c4 * 4) =
                *(const float4*)(stage + m * ST + c4 * 4);
        }
    } else if (EPI == 1) {
        // trop (cols 32-63) and real (cols 64-95)
#pragma unroll
        for (int i = 0; i < ROWS / 16; i++) {
            int idx = i * 256 + tid; int m = idx >> 4, c4 = idx & 15;
            float4 v = *(const float4*)(stage + m * ST + 32 + c4 * 4);
            if (c4 < 8) *(float4*)(po0 + (size_t)(row0 + m) * 32 + c4 * 4) = v;
            else        *(float4*)(po1 + (size_t)(row0 + m) * 32 + (c4 - 8) * 4) = v;
        }
        // boolean bits (cols 0-31) with exact fp32 fixup near zero
        if (tid < ROWS) {
            const int row = row0 + tid;
            unsigned bits = 0;
#pragma unroll 4
            for (int j = 0; j < 32; j++) {
                float v = stage[tid * ST + j];
                if (fabsf(v) < 2e-3f) {
                    const float* xr = A + (size_t)row * 1024;
                    const float* wr = BT + (size_t)j * 1024;
                    float s = 0.f;
#pragma unroll 8
                    for (int k = 0; k < 1024; k++) s = fmaf(xr[k], wr[k], s);
                    v = s;
                }
                bits |= (v > 0.f ? 1u : 0u) << j;
            }
            po2[row] = bits;
        }
    } else { // EPI == 2: transpose store vpT[(b*128+h)][m]
        const int b = row0 >> 10;
        const int m0 = row0 & 1023;
        const int h = tid & 127, half = tid >> 7;
        constexpr int MH = ROWS / 2;
        float* vpt = po0 + ((size_t)b * 128 + h) * 1024 + m0 + half * MH;
#pragma unroll 4
        for (int mm = 0; mm < MH; mm += 4) {
            int mb = half * MH + mm;
            float4 v = make_float4(stage[(mb + 0) * ST + h], stage[(mb + 1) * ST + h],
                                   stage[(mb + 2) * ST + h], stage[(mb + 3) * ST + h]);
            *(float4*)(vpt + mm) = v;
        }
    }
}

// ================================================================
// W transpose prep: wqT[j][d], wkT[j][d] (96x1024), wvT[h][d] (128x1024)
// ================================================================
__global__ __launch_bounds__(256) void wprep_kernel(
    const float* __restrict__ Wqb, const float* __restrict__ Wqt, const float* __restrict__ Wqr,
    const float* __restrict__ Wkb, const float* __restrict__ Wkt, const float* __restrict__ Wkr,
    const float* __restrict__ Wv)
{
    int i = blockIdx.x * 256 + threadIdx.x;
    const int NQ = 96 * 1024;
    if (i < NQ) {
        int j = i >> 10, d = i & 1023;
        const float* W = (j < 32) ? Wqb : ((j < 64) ? Wqt : Wqr);
        g_wqT[i] = W[(size_t)d * 32 + (j & 31)];
    } else if (i < 2 * NQ) {
        int ii = i - NQ;
        int j = ii >> 10, d = ii & 1023;
        const float* W = (j < 32) ? Wkb : ((j < 64) ? Wkt : Wkr);
        g_wkT[ii] = W[(size_t)d * 32 + (j & 31)];
    } else if (i < 2 * NQ + 128 * 1024) {
        int ii = i - 2 * NQ;
        int j = ii >> 10, d = ii & 1023;
        g_wvT[ii] = Wv[(size_t)d * 128 + j];
    }
}

// ================================================================
// Fused monoid scores (unchanged)
// ================================================================
__global__ __launch_bounds__(256) void scores_kernel(
    const float* __restrict__ fw, const int* __restrict__ mask,
    float* __restrict__ attn)
{
    __shared__ float qt[64][32];
    __shared__ float qr[64][32];
    __shared__ float kts[32][68];
    __shared__ float krs[32][68];
    __shared__ unsigned qb_s[64];
    __shared__ unsigned kb_s[64];

    const int tid = threadIdx.x;
    const int b  = blockIdx.z;
    const int n0 = blockIdx.y * 64;
    const int m0 = blockIdx.x * 64;
    const int qbase = b * Nc + n0;
    const int kbase = b * Mc + m0;

#pragma unroll
    for (int l = 0; l < 2; l++) {
        int idx = tid + l * 256;
        int r = idx >> 3, c = (idx & 7) * 4;
        *(float4*)&qt[r][c] = *(const float4*)(g_qt + (size_t)(qbase + r) * MBITS + c);
        *(float4*)&qr[r][c] = *(const float4*)(g_qr + (size_t)(qbase + r) * MBITS + c);
    }
#pragma unroll
    for (int l = 0; l < 8; l++) {
        int idx = tid + l * 256;
        int r = idx >> 5, d = idx & 31;
        kts[d][r] = g_kt[(size_t)(kbase + r) * MBITS + d];
        krs[d][r] = g_kr[(size_t)(kbase + r) * MBITS + d];
    }
    if (tid < 64)            qb_s[tid]       = g_qb[qbase + tid];
    else if (tid < 128)      kb_s[tid - 64]  = g_kb[kbase + tid - 64];
    __syncthreads();

    const int tn0 = (tid >> 4) * 4;
    const int tm0 = (tid & 15) * 4;

    float tAcc[4][4], rAcc[4][4];
#pragma unroll
    for (int i = 0; i < 4; i++)
#pragma unroll
        for (int j = 0; j < 4; j++) { tAcc[i][j] = NEG_INF; rAcc[i][j] = 0.f; }

#pragma unroll
    for (int d0 = 0; d0 < 32; d0 += 4) {
        float qtl[4][4], qrl[4][4];
#pragma unroll
        for (int i = 0; i < 4; i++) {
            float4 t = *(float4*)&qt[tn0 + i][d0];
            float4 r = *(float4*)&qr[tn0 + i][d0];
            qtl[i][0] = t.x; qtl[i][1] = t.y; qtl[i][2] = t.z; qtl[i][3] = t.w;
            qrl[i][0] = r.x; qrl[i][1] = r.y; qrl[i][2] = r.z; qrl[i][3] = r.w;
        }
#pragma unroll
        for (int dd = 0; dd < 4; dd++) {
            float4 ktv = *(float4*)&kts[d0 + dd][tm0];
            float4 krv = *(float4*)&krs[d0 + dd][tm0];
            float ktl[4] = {ktv.x, ktv.y, ktv.z, ktv.w};
            float krl[4] = {krv.x, krv.y, krv.z, krv.w};
#pragma unroll
            for (int i = 0; i < 4; i++) {
                float qtd = qtl[i][dd];
                float qrd = qrl[i][dd];
#pragma unroll
                for (int j = 0; j < 4; j++) {
                    tAcc[i][j] = fmaxf(tAcc[i][j], qtd + ktl[j]);
                    rAcc[i][j] = fmaf(qrd, krl[j], rAcc[i][j]);
                }
            }
        }
    }

    float f0 = fw[0], f1 = fw[1], f2 = fw[2];
    float fm = fmaxf(f0, fmaxf(f1, f2));
    float e0 = __expf(f0 - fm), e1 = __expf(f1 - fm), e2 = __expf(f2 - fm);
    float inv = 1.f / (e0 + e1 + e2);
    float w0 = e0 * inv, w1 = e1 * inv, w2 = e2 * inv;

    unsigned qbv[4], kbv[4];
#pragma unroll
    for (int i = 0; i < 4; i++) qbv[i] = qb_s[tn0 + i];
#pragma unroll
    for (int j = 0; j < 4; j++) kbv[j] = kb_s[tm0 + j];

#pragma unroll
    for (int i = 0; i < 4; i++) {
        size_t off = ((size_t)b * Nc + n0 + tn0 + i) * Mc + m0 + tm0;
        int4 mk = *(const int4*)(mask + off);
        float s0 = (w0 * (float)(32 - __popc(qbv[i] ^ kbv[0])) + w1 * tAcc[i][0] + w2 * rAcc[i][0]) * kScale;
        float s1 = (w0 * (float)(32 - __popc(qbv[i] ^ kbv[1])) + w1 * tAcc[i][1] + w2 * rAcc[i][1]) * kScale;
        float s2 = (w0 * (float)(32 - __popc(qbv[i] ^ kbv[2])) + w1 * tAcc[i][2] + w2 * rAcc[i][2]) * kScale;
        float s3 = (w0 * (float)(32 - __popc(qbv[i] ^ kbv[3])) + w1 * tAcc[i][3] + w2 * rAcc[i][3]) * kScale;
        float4 o;
        o.x = (mk.x == 0) ? NEG_INF : s0;
        o.y = (mk.y == 0) ? NEG_INF : s1;
        o.z = (mk.z == 0) ? NEG_INF : s2;
        o.w = (mk.w == 0) ? NEG_INF : s3;
        *(float4*)(attn + off) = o;
    }
}

// ================================================================
// Row softmax over M=1024 in place (unchanged)
// ================================================================
__global__ __launch_bounds__(256) void softmax_kernel(float* __restrict__ attn)
{
    __shared__ float red[8];
    const size_t row = blockIdx.x;
    float* p = attn + row * (size_t)Mc;
    const int tid = threadIdx.x;
    const int lane = tid & 31, wid = tid >> 5;

    float4 v = *(float4*)(p + tid * 4);
    float m = fmaxf(fmaxf(v.x, v.y), fmaxf(v.z, v.w));
#pragma unroll
    for (int o = 16; o > 0; o >>= 1) m = fmaxf(m, __shfl_xor_sync(0xffffffffu, m, o));
    if (lane == 0) red[wid] = m;
    __syncthreads();
    float bm = fmaxf(fmaxf(fmaxf(red[0], red[1]), fmaxf(red[2], red[3])),
                     fmaxf(fmaxf(red[4], red[5]), fmaxf(red[6], red[7])));
    __syncthreads();

    float4 e;
    e.x = __expf(v.x - bm); e.y = __expf(v.y - bm);
    e.z = __expf(v.z - bm); e.w = __expf(v.w - bm);
    float s = e.x + e.y + e.z + e.w;
#pragma unroll
    for (int o = 16; o > 0; o >>= 1) s += __shfl_xor_sync(0xffffffffu, s, o);
    if (lane == 0) red[wid] = s;
    __syncthreads();
    float ts = red[0] + red[1] + red[2] + red[3] + red[4] + red[5] + red[6] + red[7];
    float invs = 1.f / ts;
    e.x *= invs; e.y *= invs; e.z *= invs; e.w *= invs;
    *(float4*)(p + tid * 4) = e;
}

// ================================================================
extern "C" void kernel_launch(void* const* d_in, const int* in_sizes, int n_in,
                              void* d_out, int out_size)
{
    const float* Q    = (const float*)d_in[0];
    const float* K    = (const float*)d_in[1];
    const float* V    = (const float*)d_in[2];
    const float* Wqb  = (const float*)d_in[3];
    const float* Wkb  = (const float*)d_in[4];
    const float* Wqt  = (const float*)d_in[5];
    const float* Wkt  = (const float*)d_in[6];
    const float* Wqr  = (const float*)d_in[7];
    const float* Wkr  = (const float*)d_in[8];
    const float* Wv   = (const float*)d_in[9];
    const float* fw   = (const float*)d_in[10];
    const int*   mask = (const int*)d_in[11];

    float* out  = (float*)d_out;                         // [B,N,128]
    float* attn = (float*)d_out + (size_t)Bc * Nc * Hc;  // [B,N,M]

    float *qt, *qr, *kt, *kr, *wqT, *wkT, *wvT, *vpT;
    unsigned *qb, *kb;
    cudaGetSymbolAddress((void**)&qt, g_qt);
    cudaGetSymbolAddress((void**)&qr, g_qr);
    cudaGetSymbolAddress((void**)&qb, g_qb);
    cudaGetSymbolAddress((void**)&kt, g_kt);
    cudaGetSymbolAddress((void**)&kr, g_kr);
    cudaGetSymbolAddress((void**)&kb, g_kb);
    cudaGetSymbolAddress((void**)&wqT, g_wqT);
    cudaGetSymbolAddress((void**)&wkT, g_wkT);
    cudaGetSymbolAddress((void**)&wvT, g_wvT);
    cudaGetSymbolAddress((void**)&vpT, g_vpT);

    // smem: A hi/lo x2bufs + B hi/lo x2bufs (80B per row)
    const int SMEM96T2  = 4 * 128 * 80 + 4 * 96 * 80;   // 71680 (proj, 128-row tiles)
    const int SMEM128T1 = 4 * 64 * 80 + 4 * 128 * 80;   // 61440 (VP/out, 64-row tiles)
    cudaFuncSetAttribute(mma_kernel<96, 1, 2>,  cudaFuncAttributeMaxDynamicSharedMemorySize, SMEM96T2);
    cudaFuncSetAttribute(mma_kernel<128, 2, 1>, cudaFuncAttributeMaxDynamicSharedMemorySize, SMEM128T1);
    cudaFuncSetAttribute(mma_kernel<128, 0, 1>, cudaFuncAttributeMaxDynamicSharedMemorySize, SMEM128T1);

    // 1. weight transposes
    wprep_kernel<<<1280, 256>>>(Wqb, Wqt, Wqr, Wkb, Wkt, Wkr, Wv);

    // 2. Q + K projections (split-bf16 HMMA), 128-row tiles, 64 per side -> 128 CTAs
    mma_kernel<96, 1, 2><<<128, 256, SMEM96T2>>>(
        Q, wqT, qt, qr, qb, K, wkT, kt, kr, kb, 64, 0);

    // 3. VP = V @ Wv, 64-row tiles -> 128 CTAs (full wave), transposed store
    mma_kernel<128, 2, 1><<<128, 256, SMEM128T1>>>(
        V, wvT, vpT, nullptr, nullptr, nullptr, nullptr, nullptr, nullptr, nullptr, 128, 0);

    // 4. fused monoid scores (masked, scaled)
    scores_kernel<<<dim3(16, 16, 8), 256>>>(fw, mask, attn);

    // 5. softmax over M
    softmax_kernel<<<Bc * Nc, 256>>>(attn);

    // 6. out = attn @ VP, 64-row tiles -> 128 CTAs (full wave), batched B via vpT
    mma_kernel<128, 0, 1><<<128, 256, SMEM128T1>>>(
        attn, vpT, out, nullptr, nullptr, nullptr, nullptr, nullptr, nullptr, nullptr, 128, 1);
}